// round 5
// baseline (speedup 1.0000x reference)
#include <cuda_runtime.h>
#include <math.h>

#define BATCH 8
#define CHN   64
#define HEADS 4
#define CHH   16
#define IMG   256
#define HW    65536
#define NTOT  (BATCH*CHN*HW)

typedef unsigned long long ull;

// ---------------- packed f32x2 helpers -------------------------------------
__device__ __forceinline__ ull pk2(float lo, float hi) {
    ull r;
    asm("mov.b64 %0, {%1, %2};" : "=l"(r) : "f"(lo), "f"(hi));
    return r;
}
__device__ __forceinline__ void unpk2(ull v, float& lo, float& hi) {
    asm("mov.b64 {%0, %1}, %2;" : "=f"(lo), "=f"(hi) : "l"(v));
}
__device__ __forceinline__ ull fma2(ull a, ull b, ull c) {
    ull d;
    asm("fma.rn.f32x2 %0, %1, %2, %3;" : "=l"(d) : "l"(a), "l"(b), "l"(c));
    return d;
}

// ---------------- scratch (device globals; no allocation allowed) ----------
__device__ float g_Q[NTOT];
__device__ float g_K[NTOT];
__device__ float g_V[NTOT];
__device__ float g_T[NTOT];
__device__ float g_partial[32*32*256];  // [split][bh][c*16+d]
__device__ float g_attn[32*256];        // [bh][c*16+d]
__device__ float g_norms[2*BATCH*CHN];  // [0:512)=q norms, [512:1024)=k norms

// ---------------- 1x1 conv: out[b,co,n] = sum_ci W[co,ci]*src[b,ci,n]+bias --
__global__ void conv1x1_kernel(const float* __restrict__ src,
                               const float* __restrict__ w,
                               const float* __restrict__ bias,
                               float* __restrict__ dst) {
    __shared__ __align__(16) float Wt[64*64];   // [ci][co]
    __shared__ __align__(16) float Xs[64*64];   // [ci][px]
    const int b = blockIdx.z;
    const int pxbase = blockIdx.x * 64;
    const int tid = threadIdx.x;

    for (int e = tid; e < 4096; e += 256) {
        int ci = e >> 6, co = e & 63;
        Wt[ci*64 + co] = w[co*64 + ci];
    }
    for (int e = tid; e < 4096; e += 256) {
        int ci = e >> 6, px = e & 63;
        Xs[ci*64 + px] = src[((b*64 + ci) << 16) + pxbase + px];
    }
    __syncthreads();

    const int ty = tid >> 4, tx = tid & 15;
    const int co0 = ty*4, px0 = tx*4;
    ull acc[4][2];
    #pragma unroll
    for (int i = 0; i < 4; i++) {
        float bv = bias[co0 + i];
        acc[i][0] = pk2(bv, bv);
        acc[i][1] = pk2(bv, bv);
    }
    #pragma unroll 8
    for (int ci = 0; ci < 64; ci++) {
        float4 a4 = *(const float4*)&Wt[ci*64 + co0];
        float4 b4 = *(const float4*)&Xs[ci*64 + px0];
        ull bp0 = pk2(b4.x, b4.y);
        ull bp1 = pk2(b4.z, b4.w);
        float av[4] = {a4.x, a4.y, a4.z, a4.w};
        #pragma unroll
        for (int i = 0; i < 4; i++) {
            ull ad = pk2(av[i], av[i]);
            acc[i][0] = fma2(ad, bp0, acc[i][0]);
            acc[i][1] = fma2(ad, bp1, acc[i][1]);
        }
    }
    #pragma unroll
    for (int i = 0; i < 4; i++) {
        float4 o;
        unpk2(acc[i][0], o.x, o.y);
        unpk2(acc[i][1], o.z, o.w);
        *(float4*)&dst[((b*64 + co0 + i) << 16) + pxbase + px0] = o;
    }
}

// ---------------- per-row sum of squares for q/k L2 norms ------------------
__global__ void norms_kernel() {
    const int idx = blockIdx.x;           // 0..1023
    const float* base = (idx < 512) ? g_Q : g_K;
    const int row = idx & 511;
    const float4* p = (const float4*)(base + ((size_t)row << 16));
    const int tid = threadIdx.x;
    float s = 0.f;
    for (int i = tid; i < HW/4; i += 256) {
        float4 v = p[i];
        s += v.x*v.x + v.y*v.y + v.z*v.z + v.w*v.w;
    }
    #pragma unroll
    for (int o = 16; o; o >>= 1) s += __shfl_xor_sync(0xffffffffu, s, o);
    __shared__ float red[8];
    if ((tid & 31) == 0) red[tid >> 5] = s;
    __syncthreads();
    if (tid < 8) {
        float v = red[tid];
        #pragma unroll
        for (int o = 4; o; o >>= 1) v += __shfl_xor_sync(0xffu, v, o);
        if (tid == 0) g_norms[idx] = fmaxf(sqrtf(v), 1e-12f);
    }
}

// ---------------- q.k^T partial sums (split over n) ------------------------
__global__ void attn_partial_kernel() {
    __shared__ __align__(16) float Qs[16*132];
    __shared__ __align__(16) float Ks[16*132];
    const int bh = blockIdx.x;       // 0..31
    const int split = blockIdx.y;    // 0..31
    const int b = bh >> 2, h = bh & 3;
    const int tid = threadIdx.x;
    const int c = tid >> 4, d = tid & 15;
    const float* Qb = g_Q + (((size_t)(b*64 + h*16)) << 16);
    const float* Kb = g_K + (((size_t)(b*64 + h*16)) << 16);
    float acc = 0.f;
    const int nbase0 = split * 2048;
    #pragma unroll 1
    for (int sub = 0; sub < 16; sub++) {
        const int nb = nbase0 + sub*128;
        for (int e = tid; e < 2048; e += 256) {
            int ch = e >> 7, j = e & 127;
            Qs[ch*132 + j] = Qb[(ch << 16) + nb + j];
            Ks[ch*132 + j] = Kb[(ch << 16) + nb + j];
        }
        __syncthreads();
        const float* qrow = &Qs[c*132];
        const float* krow = &Ks[d*132];
        #pragma unroll
        for (int j = 0; j < 128; j += 4) {
            float4 qa = *(const float4*)&qrow[j];
            float4 ka = *(const float4*)&krow[j];
            acc += qa.x*ka.x + qa.y*ka.y + qa.z*ka.z + qa.w*ka.w;
        }
        __syncthreads();
    }
    g_partial[(split*32 + bh)*256 + tid] = acc;
}

// ---------------- reduce partials, apply norms, softmax --------------------
__global__ void attn_finish_kernel() {
    const int bh = blockIdx.x;
    const int b = bh >> 2, h = bh & 3;
    const int tid = threadIdx.x;
    const int c = tid >> 4, d = tid & 15;
    float s = 0.f;
    #pragma unroll
    for (int sp = 0; sp < 32; sp++) s += g_partial[(sp*32 + bh)*256 + tid];
    const float qn = g_norms[b*64 + h*16 + c];
    const float kn = g_norms[512 + b*64 + h*16 + d];
    float val = s / (qn * kn);
    // softmax over d: 16-lane groups (xor shuffles stay within the group)
    float m = val;
    #pragma unroll
    for (int o = 8; o; o >>= 1) m = fmaxf(m, __shfl_xor_sync(0xffffffffu, m, o));
    float e = expf(val - m);
    float sum = e;
    #pragma unroll
    for (int o = 8; o; o >>= 1) sum += __shfl_xor_sync(0xffffffffu, sum, o);
    g_attn[bh*256 + tid] = e / sum;
}

// ---------------- out[b,h,c,n] = sum_d attn[c,d] * V[b,h,d,n] --------------
__global__ void applyv_kernel() {
    __shared__ float As[256];
    const int b = blockIdx.z, h = blockIdx.y;
    const int tid = threadIdx.x;
    const int px0 = blockIdx.x*512 + tid*2;
    As[tid] = g_attn[(b*4 + h)*256 + tid];
    __syncthreads();
    const float* Vb = g_V + (((size_t)(b*64 + h*16)) << 16);
    ull acc[16];
    #pragma unroll
    for (int cc = 0; cc < 16; cc++) acc[cc] = 0ull;
    #pragma unroll
    for (int d = 0; d < 16; d++) {
        float2 v2 = *(const float2*)&Vb[(d << 16) + px0];
        ull vp = pk2(v2.x, v2.y);
        #pragma unroll
        for (int cc = 0; cc < 16; cc++) {
            float a = As[cc*16 + d];
            acc[cc] = fma2(pk2(a, a), vp, acc[cc]);
        }
    }
    float* Ob = g_T + (((size_t)(b*64 + h*16)) << 16);
    #pragma unroll
    for (int cc = 0; cc < 16; cc++) {
        float2 o;
        unpk2(acc[cc], o.x, o.y);
        *(float2*)&Ob[(cc << 16) + px0] = o;
    }
}

// ---------------- 3x3 conv, f32x2 packed, fused bias/relu/residual ---------
// Tile: 32x8 px, all 64 oc. 256 threads: tx(4) x ty(8) x toc(8).
// Each thread: 8 px (x-contig) x 8 oc; acc packed over oc pairs.
__global__ void __launch_bounds__(256, 2)
conv3x3_kernel(const float* __restrict__ src,
               const float* __restrict__ w,
               const float* __restrict__ bias,
               float* __restrict__ dst,
               const float* __restrict__ add1,
               const float* __restrict__ add2,
               int relu) {
    __shared__ __align__(16) float xs[10*36];   // 10 rows x 34 cols used, pitch 36
    __shared__ __align__(16) float ws[9*64];    // [tap][oc]
    const int tid = threadIdx.x;
    const int toc = tid >> 5;          // 0..7
    const int ty  = (tid >> 2) & 7;    // 0..7
    const int tx  = tid & 3;           // 0..3
    const int x0 = blockIdx.x * 32, y0 = blockIdx.y * 8;
    const int b  = blockIdx.z;
    const int oc0 = toc * 8;

    ull acc[8][4];                // [px][oc pair]; pair = (oc0+2j, oc0+2j+1)
    #pragma unroll
    for (int p = 0; p < 8; p++)
        #pragma unroll
        for (int j = 0; j < 4; j++) acc[p][j] = 0ull;

    #pragma unroll 1
    for (int ci = 0; ci < 64; ci++) {
        const float* sp = src + (((size_t)(b*64 + ci)) << 16);
        // xs: rows y0-1..y0+8 (10), cols x0-1..x0+32 (34)
        for (int e = tid; e < 340; e += 256) {
            int r = e / 34;
            int cidx = e - r*34;
            int gy = y0 + r - 1, gx = x0 + cidx - 1;
            float v = 0.f;
            if (gy >= 0 && gy < 256 && gx >= 0 && gx < 256)
                v = sp[(gy << 8) + gx];
            xs[r*36 + cidx] = v;
        }
        // ws[t*64 + oc] = w[oc][ci][t]
        for (int e = tid; e < 576; e += 256) {
            int oc = e / 9, t = e - oc*9;
            ws[t*64 + oc] = w[oc*576 + ci*9 + t];
        }
        __syncthreads();

        #pragma unroll
        for (int tr = 0; tr < 3; tr++) {
            const float* xrow = &xs[(ty + tr)*36 + 8*tx];
            float4 a = *(const float4*)&xrow[0];
            float4 bb = *(const float4*)&xrow[4];
            float4 cc = *(const float4*)&xrow[8];
            float xv[12] = {a.x, a.y, a.z, a.w, bb.x, bb.y, bb.z, bb.w,
                            cc.x, cc.y, cc.z, cc.w};
            ull xd[10];
            #pragma unroll
            for (int c = 0; c < 10; c++) xd[c] = pk2(xv[c], xv[c]);
            #pragma unroll
            for (int tc = 0; tc < 3; tc++) {
                const int t = tr*3 + tc;
                const ull* wp = (const ull*)&ws[t*64 + oc0];
                ull w0 = wp[0], w1 = wp[1], w2 = wp[2], w3 = wp[3];
                #pragma unroll
                for (int p = 0; p < 8; p++) {
                    ull xvv = xd[p + tc];
                    acc[p][0] = fma2(w0, xvv, acc[p][0]);
                    acc[p][1] = fma2(w1, xvv, acc[p][1]);
                    acc[p][2] = fma2(w2, xvv, acc[p][2]);
                    acc[p][3] = fma2(w3, xvv, acc[p][3]);
                }
            }
        }
        __syncthreads();
    }

    const int gy = y0 + ty;
    #pragma unroll
    for (int p = 0; p < 8; p++) {
        const int gx = x0 + 8*tx + p;
        const int pidx = (gy << 8) + gx;
        #pragma unroll
        for (int j = 0; j < 4; j++) {
            const int oc = oc0 + 2*j;
            float v0, v1;
            unpk2(acc[p][j], v0, v1);
            v0 += bias[oc];
            v1 += bias[oc + 1];
            if (relu) { v0 = fmaxf(v0, 0.f); v1 = fmaxf(v1, 0.f); }
            size_t i0 = (((size_t)(b*64 + oc)) << 16) + pidx;
            size_t i1 = (((size_t)(b*64 + oc + 1)) << 16) + pidx;
            if (add1) { v0 += add1[i0]; v1 += add1[i1]; }
            if (add2) { v0 += add2[i0]; v1 += add2[i1]; }
            dst[i0] = v0;
            dst[i1] = v1;
        }
    }
}

// ---------------------------------------------------------------------------
static float* sym_addr(const void* sym) {
    void* p = nullptr;
    cudaGetSymbolAddress(&p, sym);
    return (float*)p;
}

extern "C" void kernel_launch(void* const* d_in, const int* in_sizes, int n_in,
                              void* d_out, int out_size) {
    const float* x    = (const float*)d_in[0];
    const float* y    = (const float*)d_in[1];
    const float* qw   = (const float*)d_in[2];
    const float* qb   = (const float*)d_in[3];
    const float* kw   = (const float*)d_in[4];
    const float* kb   = (const float*)d_in[5];
    const float* vw   = (const float*)d_in[6];
    const float* vb   = (const float*)d_in[7];
    const float* r1w1 = (const float*)d_in[8];
    const float* r1b1 = (const float*)d_in[9];
    const float* r1w2 = (const float*)d_in[10];
    const float* r1b2 = (const float*)d_in[11];
    const float* r2w1 = (const float*)d_in[12];
    const float* r2b1 = (const float*)d_in[13];
    const float* r2w2 = (const float*)d_in[14];
    const float* r2b2 = (const float*)d_in[15];
    float* out = (float*)d_out;

    float* pQ = sym_addr(g_Q);
    float* pK = sym_addr(g_K);
    float* pV = sym_addr(g_V);
    float* pT = sym_addr(g_T);

    dim3 blk(256);

    // QKV 1x1 convs
    conv1x1_kernel<<<dim3(1024, 1, 8), blk>>>(x, qw, qb, pQ);
    conv1x1_kernel<<<dim3(1024, 1, 8), blk>>>(y, kw, kb, pK);
    conv1x1_kernel<<<dim3(1024, 1, 8), blk>>>(y, vw, vb, pV);

    // norms + attention
    norms_kernel<<<1024, blk>>>();
    attn_partial_kernel<<<dim3(32, 32), blk>>>();
    attn_finish_kernel<<<32, blk>>>();
    applyv_kernel<<<dim3(128, 4, 8), blk>>>();   // -> g_T

    dim3 cgrid(8, 32, 8);
    // residual block 1: T -> Q (relu), then K = T + conv(Q)
    conv3x3_kernel<<<cgrid, blk>>>(pT, r1w1, r1b1, pQ, nullptr, nullptr, 1);
    conv3x3_kernel<<<cgrid, blk>>>(pQ, r1w2, r1b2, pK, pT, nullptr, 0);
    // residual block 2: K -> Q (relu), then out = K + conv(Q) + y
    conv3x3_kernel<<<cgrid, blk>>>(pK, r2w1, r2b1, pQ, nullptr, nullptr, 1);
    conv3x3_kernel<<<cgrid, blk>>>(pQ, r2w2, r2b2, out, pK, y, 0);
}

// round 6
// speedup vs baseline: 1.0414x; 1.0414x over previous
#include <cuda_runtime.h>
#include <math.h>

#define BATCH 8
#define CHN   64
#define HEADS 4
#define CHH   16
#define IMG   256
#define HW    65536
#define NTOT  (BATCH*CHN*HW)

typedef unsigned long long ull;

// ---------------- packed f32x2 helpers -------------------------------------
__device__ __forceinline__ ull pk2(float lo, float hi) {
    ull r;
    asm("mov.b64 %0, {%1, %2};" : "=l"(r) : "f"(lo), "f"(hi));
    return r;
}
__device__ __forceinline__ void unpk2(ull v, float& lo, float& hi) {
    asm("mov.b64 {%0, %1}, %2;" : "=f"(lo), "=f"(hi) : "l"(v));
}
__device__ __forceinline__ ull fma2(ull a, ull b, ull c) {
    ull d;
    asm("fma.rn.f32x2 %0, %1, %2, %3;" : "=l"(d) : "l"(a), "l"(b), "l"(c));
    return d;
}

// ---------------- scratch (device globals; no allocation allowed) ----------
__device__ float g_Q[NTOT];
__device__ float g_K[NTOT];
__device__ float g_V[NTOT];
__device__ float g_T[NTOT];
__device__ float g_partial[32*32*256];  // [split][bh][c*16+d]
__device__ float g_attn[32*256];        // [bh][c*16+d]
__device__ float g_norms[2*BATCH*CHN];  // [0:512)=q norms, [512:1024)=k norms

// ---------------- 1x1 conv: out[b,co,n] = sum_ci W[co,ci]*src[b,ci,n]+bias --
__global__ void conv1x1_kernel(const float* __restrict__ src,
                               const float* __restrict__ w,
                               const float* __restrict__ bias,
                               float* __restrict__ dst) {
    __shared__ __align__(16) float Wt[64*64];   // [ci][co]
    __shared__ __align__(16) float Xs[64*64];   // [ci][px]
    const int b = blockIdx.z;
    const int pxbase = blockIdx.x * 64;
    const int tid = threadIdx.x;

    for (int e = tid; e < 4096; e += 256) {
        int ci = e >> 6, co = e & 63;
        Wt[ci*64 + co] = w[co*64 + ci];
    }
    for (int e = tid; e < 4096; e += 256) {
        int ci = e >> 6, px = e & 63;
        Xs[ci*64 + px] = src[((b*64 + ci) << 16) + pxbase + px];
    }
    __syncthreads();

    const int ty = tid >> 4, tx = tid & 15;
    const int co0 = ty*4, px0 = tx*4;
    ull acc[4][2];
    #pragma unroll
    for (int i = 0; i < 4; i++) {
        float bv = bias[co0 + i];
        acc[i][0] = pk2(bv, bv);
        acc[i][1] = pk2(bv, bv);
    }
    #pragma unroll 8
    for (int ci = 0; ci < 64; ci++) {
        float4 a4 = *(const float4*)&Wt[ci*64 + co0];
        float4 b4 = *(const float4*)&Xs[ci*64 + px0];
        ull bp0 = pk2(b4.x, b4.y);
        ull bp1 = pk2(b4.z, b4.w);
        float av[4] = {a4.x, a4.y, a4.z, a4.w};
        #pragma unroll
        for (int i = 0; i < 4; i++) {
            ull ad = pk2(av[i], av[i]);
            acc[i][0] = fma2(ad, bp0, acc[i][0]);
            acc[i][1] = fma2(ad, bp1, acc[i][1]);
        }
    }
    #pragma unroll
    for (int i = 0; i < 4; i++) {
        float4 o;
        unpk2(acc[i][0], o.x, o.y);
        unpk2(acc[i][1], o.z, o.w);
        *(float4*)&dst[((b*64 + co0 + i) << 16) + pxbase + px0] = o;
    }
}

// ---------------- per-row sum of squares for q/k L2 norms ------------------
__global__ void norms_kernel() {
    const int idx = blockIdx.x;           // 0..1023
    const float* base = (idx < 512) ? g_Q : g_K;
    const int row = idx & 511;
    const float4* p = (const float4*)(base + ((size_t)row << 16));
    const int tid = threadIdx.x;
    float s = 0.f;
    for (int i = tid; i < HW/4; i += 256) {
        float4 v = p[i];
        s += v.x*v.x + v.y*v.y + v.z*v.z + v.w*v.w;
    }
    #pragma unroll
    for (int o = 16; o; o >>= 1) s += __shfl_xor_sync(0xffffffffu, s, o);
    __shared__ float red[8];
    if ((tid & 31) == 0) red[tid >> 5] = s;
    __syncthreads();
    if (tid < 8) {
        float v = red[tid];
        #pragma unroll
        for (int o = 4; o; o >>= 1) v += __shfl_xor_sync(0xffu, v, o);
        if (tid == 0) g_norms[idx] = fmaxf(sqrtf(v), 1e-12f);
    }
}

// ---------------- q.k^T partial sums (split over n) ------------------------
__global__ void attn_partial_kernel() {
    __shared__ __align__(16) float Qs[16*132];
    __shared__ __align__(16) float Ks[16*132];
    const int bh = blockIdx.x;       // 0..31
    const int split = blockIdx.y;    // 0..31
    const int b = bh >> 2, h = bh & 3;
    const int tid = threadIdx.x;
    const int c = tid >> 4, d = tid & 15;
    const float* Qb = g_Q + (((size_t)(b*64 + h*16)) << 16);
    const float* Kb = g_K + (((size_t)(b*64 + h*16)) << 16);
    float acc = 0.f;
    const int nbase0 = split * 2048;
    #pragma unroll 1
    for (int sub = 0; sub < 16; sub++) {
        const int nb = nbase0 + sub*128;
        for (int e = tid; e < 2048; e += 256) {
            int ch = e >> 7, j = e & 127;
            Qs[ch*132 + j] = Qb[(ch << 16) + nb + j];
            Ks[ch*132 + j] = Kb[(ch << 16) + nb + j];
        }
        __syncthreads();
        const float* qrow = &Qs[c*132];
        const float* krow = &Ks[d*132];
        #pragma unroll
        for (int j = 0; j < 128; j += 4) {
            float4 qa = *(const float4*)&qrow[j];
            float4 ka = *(const float4*)&krow[j];
            acc += qa.x*ka.x + qa.y*ka.y + qa.z*ka.z + qa.w*ka.w;
        }
        __syncthreads();
    }
    g_partial[(split*32 + bh)*256 + tid] = acc;
}

// ---------------- reduce partials, apply norms, softmax --------------------
__global__ void attn_finish_kernel() {
    const int bh = blockIdx.x;
    const int b = bh >> 2, h = bh & 3;
    const int tid = threadIdx.x;
    const int c = tid >> 4, d = tid & 15;
    float s = 0.f;
    #pragma unroll
    for (int sp = 0; sp < 32; sp++) s += g_partial[(sp*32 + bh)*256 + tid];
    const float qn = g_norms[b*64 + h*16 + c];
    const float kn = g_norms[512 + b*64 + h*16 + d];
    float val = s / (qn * kn);
    // softmax over d: 16-lane groups (xor shuffles stay within the group)
    float m = val;
    #pragma unroll
    for (int o = 8; o; o >>= 1) m = fmaxf(m, __shfl_xor_sync(0xffffffffu, m, o));
    float e = expf(val - m);
    float sum = e;
    #pragma unroll
    for (int o = 8; o; o >>= 1) sum += __shfl_xor_sync(0xffffffffu, sum, o);
    g_attn[bh*256 + tid] = e / sum;
}

// ---------------- out[b,h,c,n] = sum_d attn[c,d] * V[b,h,d,n] --------------
__global__ void applyv_kernel() {
    __shared__ float As[256];
    const int b = blockIdx.z, h = blockIdx.y;
    const int tid = threadIdx.x;
    const int px0 = blockIdx.x*512 + tid*2;
    As[tid] = g_attn[(b*4 + h)*256 + tid];
    __syncthreads();
    const float* Vb = g_V + (((size_t)(b*64 + h*16)) << 16);
    ull acc[16];
    #pragma unroll
    for (int cc = 0; cc < 16; cc++) acc[cc] = 0ull;
    #pragma unroll
    for (int d = 0; d < 16; d++) {
        float2 v2 = *(const float2*)&Vb[(d << 16) + px0];
        ull vp = pk2(v2.x, v2.y);
        #pragma unroll
        for (int cc = 0; cc < 16; cc++) {
            float a = As[cc*16 + d];
            acc[cc] = fma2(pk2(a, a), vp, acc[cc]);
        }
    }
    float* Ob = g_T + (((size_t)(b*64 + h*16)) << 16);
    #pragma unroll
    for (int cc = 0; cc < 16; cc++) {
        float2 o;
        unpk2(acc[cc], o.x, o.y);
        *(float2*)&Ob[(cc << 16) + px0] = o;
    }
}

// ---------------- 3x3 conv, f32x2 packed, fused bias/relu/residual ---------
// Tile: 32x8 px, all 64 oc. 256 threads: tx(4) x ty(8) x toc(8).
// Each thread: 8 px (x-contig) x 8 oc; acc packed over oc pairs.
__global__ void __launch_bounds__(256, 2)
conv3x3_kernel(const float* __restrict__ src,
               const float* __restrict__ w,
               const float* __restrict__ bias,
               float* __restrict__ dst,
               const float* __restrict__ add1,
               const float* __restrict__ add2,
               int relu) {
    __shared__ __align__(16) float xs[10*36];   // 10 rows x 34 cols used, pitch 36
    __shared__ __align__(16) float ws[9*64];    // [tap][oc]
    const int tid = threadIdx.x;
    const int toc = tid >> 5;          // 0..7
    const int ty  = (tid >> 2) & 7;    // 0..7
    const int tx  = tid & 3;           // 0..3
    const int x0 = blockIdx.x * 32, y0 = blockIdx.y * 8;
    const int b  = blockIdx.z;
    const int oc0 = toc * 8;

    ull acc[8][4];                // [px][oc pair]; pair = (oc0+2j, oc0+2j+1)
    #pragma unroll
    for (int p = 0; p < 8; p++)
        #pragma unroll
        for (int j = 0; j < 4; j++) acc[p][j] = 0ull;

    #pragma unroll 1
    for (int ci = 0; ci < 64; ci++) {
        const float* sp = src + (((size_t)(b*64 + ci)) << 16);
        // xs: rows y0-1..y0+8 (10), cols x0-1..x0+32 (34)
        for (int e = tid; e < 340; e += 256) {
            int r = e / 34;
            int cidx = e - r*34;
            int gy = y0 + r - 1, gx = x0 + cidx - 1;
            float v = 0.f;
            if (gy >= 0 && gy < 256 && gx >= 0 && gx < 256)
                v = sp[(gy << 8) + gx];
            xs[r*36 + cidx] = v;
        }
        // ws[t*64 + oc] = w[oc][ci][t]
        for (int e = tid; e < 576; e += 256) {
            int oc = e / 9, t = e - oc*9;
            ws[t*64 + oc] = w[oc*576 + ci*9 + t];
        }
        __syncthreads();

        #pragma unroll
        for (int tr = 0; tr < 3; tr++) {
            const float* xrow = &xs[(ty + tr)*36 + 8*tx];
            float4 a = *(const float4*)&xrow[0];
            float4 bb = *(const float4*)&xrow[4];
            float4 cc = *(const float4*)&xrow[8];
            float xv[12] = {a.x, a.y, a.z, a.w, bb.x, bb.y, bb.z, bb.w,
                            cc.x, cc.y, cc.z, cc.w};
            ull xd[10];
            #pragma unroll
            for (int c = 0; c < 10; c++) xd[c] = pk2(xv[c], xv[c]);
            #pragma unroll
            for (int tc = 0; tc < 3; tc++) {
                const int t = tr*3 + tc;
                const ull* wp = (const ull*)&ws[t*64 + oc0];
                ull w0 = wp[0], w1 = wp[1], w2 = wp[2], w3 = wp[3];
                #pragma unroll
                for (int p = 0; p < 8; p++) {
                    ull xvv = xd[p + tc];
                    acc[p][0] = fma2(w0, xvv, acc[p][0]);
                    acc[p][1] = fma2(w1, xvv, acc[p][1]);
                    acc[p][2] = fma2(w2, xvv, acc[p][2]);
                    acc[p][3] = fma2(w3, xvv, acc[p][3]);
                }
            }
        }
        __syncthreads();
    }

    const int gy = y0 + ty;
    #pragma unroll
    for (int p = 0; p < 8; p++) {
        const int gx = x0 + 8*tx + p;
        const int pidx = (gy << 8) + gx;
        #pragma unroll
        for (int j = 0; j < 4; j++) {
            const int oc = oc0 + 2*j;
            float v0, v1;
            unpk2(acc[p][j], v0, v1);
            v0 += bias[oc];
            v1 += bias[oc + 1];
            if (relu) { v0 = fmaxf(v0, 0.f); v1 = fmaxf(v1, 0.f); }
            size_t i0 = (((size_t)(b*64 + oc)) << 16) + pidx;
            size_t i1 = (((size_t)(b*64 + oc + 1)) << 16) + pidx;
            if (add1) { v0 += add1[i0]; v1 += add1[i1]; }
            if (add2) { v0 += add2[i0]; v1 += add2[i1]; }
            dst[i0] = v0;
            dst[i1] = v1;
        }
    }
}

// ---------------------------------------------------------------------------
static float* sym_addr(const void* sym) {
    void* p = nullptr;
    cudaGetSymbolAddress(&p, sym);
    return (float*)p;
}

extern "C" void kernel_launch(void* const* d_in, const int* in_sizes, int n_in,
                              void* d_out, int out_size) {
    const float* x    = (const float*)d_in[0];
    const float* y    = (const float*)d_in[1];
    const float* qw   = (const float*)d_in[2];
    const float* qb   = (const float*)d_in[3];
    const float* kw   = (const float*)d_in[4];
    const float* kb   = (const float*)d_in[5];
    const float* vw   = (const float*)d_in[6];
    const float* vb   = (const float*)d_in[7];
    const float* r1w1 = (const float*)d_in[8];
    const float* r1b1 = (const float*)d_in[9];
    const float* r1w2 = (const float*)d_in[10];
    const float* r1b2 = (const float*)d_in[11];
    const float* r2w1 = (const float*)d_in[12];
    const float* r2b1 = (const float*)d_in[13];
    const float* r2w2 = (const float*)d_in[14];
    const float* r2b2 = (const float*)d_in[15];
    float* out = (float*)d_out;

    float* pQ = sym_addr(g_Q);
    float* pK = sym_addr(g_K);
    float* pV = sym_addr(g_V);
    float* pT = sym_addr(g_T);

    dim3 blk(256);

    // QKV 1x1 convs
    conv1x1_kernel<<<dim3(1024, 1, 8), blk>>>(x, qw, qb, pQ);
    conv1x1_kernel<<<dim3(1024, 1, 8), blk>>>(y, kw, kb, pK);
    conv1x1_kernel<<<dim3(1024, 1, 8), blk>>>(y, vw, vb, pV);

    // norms + attention
    norms_kernel<<<1024, blk>>>();
    attn_partial_kernel<<<dim3(32, 32), blk>>>();
    attn_finish_kernel<<<32, blk>>>();
    applyv_kernel<<<dim3(128, 4, 8), blk>>>();   // -> g_T

    dim3 cgrid(8, 32, 8);
    // residual block 1: T -> Q (relu), then K = T + conv(Q)
    conv3x3_kernel<<<cgrid, blk>>>(pT, r1w1, r1b1, pQ, nullptr, nullptr, 1);
    conv3x3_kernel<<<cgrid, blk>>>(pQ, r1w2, r1b2, pK, pT, nullptr, 0);
    // residual block 2: K -> Q (relu), then out = K + conv(Q) + y
    conv3x3_kernel<<<cgrid, blk>>>(pK, r2w1, r2b1, pQ, nullptr, nullptr, 1);
    conv3x3_kernel<<<cgrid, blk>>>(pQ, r2w2, r2b2, out, pK, y, 0);
}

// round 7
// speedup vs baseline: 1.0426x; 1.0012x over previous
#include <cuda_runtime.h>
#include <math.h>

#define BATCH 8
#define CHN   64
#define HEADS 4
#define CHH   16
#define IMG   256
#define HW    65536
#define NTOT  (BATCH*CHN*HW)

typedef unsigned long long ull;

// ---------------- packed f32x2 helpers -------------------------------------
__device__ __forceinline__ ull pk2(float lo, float hi) {
    ull r;
    asm("mov.b64 %0, {%1, %2};" : "=l"(r) : "f"(lo), "f"(hi));
    return r;
}
__device__ __forceinline__ void unpk2(ull v, float& lo, float& hi) {
    asm("mov.b64 {%0, %1}, %2;" : "=f"(lo), "=f"(hi) : "l"(v));
}
__device__ __forceinline__ ull fma2(ull a, ull b, ull c) {
    ull d;
    asm("fma.rn.f32x2 %0, %1, %2, %3;" : "=l"(d) : "l"(a), "l"(b), "l"(c));
    return d;
}

// ---------------- scratch (device globals; no allocation allowed) ----------
__device__ float g_Q[NTOT];
__device__ float g_K[NTOT];
__device__ float g_V[NTOT];
__device__ float g_T[NTOT];
__device__ float g_partial[32*32*256];  // [split][bh][c*16+d]
__device__ float g_attn[32*256];        // [bh][c*16+d]
__device__ float g_norms[2*BATCH*CHN];  // [0:512)=q norms, [512:1024)=k norms

// ---------------- 1x1 conv: out[b,co,n] = sum_ci W[co,ci]*src[b,ci,n]+bias --
__global__ void conv1x1_kernel(const float* __restrict__ src,
                               const float* __restrict__ w,
                               const float* __restrict__ bias,
                               float* __restrict__ dst) {
    __shared__ __align__(16) float Wt[64*64];   // [ci][co]
    __shared__ __align__(16) float Xs[64*64];   // [ci][px]
    const int b = blockIdx.z;
    const int pxbase = blockIdx.x * 64;
    const int tid = threadIdx.x;

    for (int e = tid; e < 4096; e += 256) {
        int ci = e >> 6, co = e & 63;
        Wt[ci*64 + co] = w[co*64 + ci];
    }
    for (int e = tid; e < 4096; e += 256) {
        int ci = e >> 6, px = e & 63;
        Xs[ci*64 + px] = src[((b*64 + ci) << 16) + pxbase + px];
    }
    __syncthreads();

    const int ty = tid >> 4, tx = tid & 15;
    const int co0 = ty*4, px0 = tx*4;
    ull acc[4][2];
    #pragma unroll
    for (int i = 0; i < 4; i++) {
        float bv = bias[co0 + i];
        acc[i][0] = pk2(bv, bv);
        acc[i][1] = pk2(bv, bv);
    }
    #pragma unroll 8
    for (int ci = 0; ci < 64; ci++) {
        float4 a4 = *(const float4*)&Wt[ci*64 + co0];
        float4 b4 = *(const float4*)&Xs[ci*64 + px0];
        ull bp0 = pk2(b4.x, b4.y);
        ull bp1 = pk2(b4.z, b4.w);
        float av[4] = {a4.x, a4.y, a4.z, a4.w};
        #pragma unroll
        for (int i = 0; i < 4; i++) {
            ull ad = pk2(av[i], av[i]);
            acc[i][0] = fma2(ad, bp0, acc[i][0]);
            acc[i][1] = fma2(ad, bp1, acc[i][1]);
        }
    }
    #pragma unroll
    for (int i = 0; i < 4; i++) {
        float4 o;
        unpk2(acc[i][0], o.x, o.y);
        unpk2(acc[i][1], o.z, o.w);
        *(float4*)&dst[((b*64 + co0 + i) << 16) + pxbase + px0] = o;
    }
}

// ---------------- per-row sum of squares for q/k L2 norms ------------------
__global__ void norms_kernel() {
    const int idx = blockIdx.x;           // 0..1023
    const float* base = (idx < 512) ? g_Q : g_K;
    const int row = idx & 511;
    const float4* p = (const float4*)(base + ((size_t)row << 16));
    const int tid = threadIdx.x;
    float s = 0.f;
    for (int i = tid; i < HW/4; i += 256) {
        float4 v = p[i];
        s += v.x*v.x + v.y*v.y + v.z*v.z + v.w*v.w;
    }
    #pragma unroll
    for (int o = 16; o; o >>= 1) s += __shfl_xor_sync(0xffffffffu, s, o);
    __shared__ float red[8];
    if ((tid & 31) == 0) red[tid >> 5] = s;
    __syncthreads();
    if (tid < 8) {
        float v = red[tid];
        #pragma unroll
        for (int o = 4; o; o >>= 1) v += __shfl_xor_sync(0xffu, v, o);
        if (tid == 0) g_norms[idx] = fmaxf(sqrtf(v), 1e-12f);
    }
}

// ---------------- q.k^T partial sums (split over n) ------------------------
__global__ void attn_partial_kernel() {
    __shared__ __align__(16) float Qs[16*132];
    __shared__ __align__(16) float Ks[16*132];
    const int bh = blockIdx.x;       // 0..31
    const int split = blockIdx.y;    // 0..31
    const int b = bh >> 2, h = bh & 3;
    const int tid = threadIdx.x;
    const int c = tid >> 4, d = tid & 15;
    const float* Qb = g_Q + (((size_t)(b*64 + h*16)) << 16);
    const float* Kb = g_K + (((size_t)(b*64 + h*16)) << 16);
    float acc = 0.f;
    const int nbase0 = split * 2048;
    #pragma unroll 1
    for (int sub = 0; sub < 16; sub++) {
        const int nb = nbase0 + sub*128;
        for (int e = tid; e < 2048; e += 256) {
            int ch = e >> 7, j = e & 127;
            Qs[ch*132 + j] = Qb[(ch << 16) + nb + j];
            Ks[ch*132 + j] = Kb[(ch << 16) + nb + j];
        }
        __syncthreads();
        const float* qrow = &Qs[c*132];
        const float* krow = &Ks[d*132];
        #pragma unroll
        for (int j = 0; j < 128; j += 4) {
            float4 qa = *(const float4*)&qrow[j];
            float4 ka = *(const float4*)&krow[j];
            acc += qa.x*ka.x + qa.y*ka.y + qa.z*ka.z + qa.w*ka.w;
        }
        __syncthreads();
    }
    g_partial[(split*32 + bh)*256 + tid] = acc;
}

// ---------------- reduce partials, apply norms, softmax --------------------
__global__ void attn_finish_kernel() {
    const int bh = blockIdx.x;
    const int b = bh >> 2, h = bh & 3;
    const int tid = threadIdx.x;
    const int c = tid >> 4, d = tid & 15;
    float s = 0.f;
    #pragma unroll
    for (int sp = 0; sp < 32; sp++) s += g_partial[(sp*32 + bh)*256 + tid];
    const float qn = g_norms[b*64 + h*16 + c];
    const float kn = g_norms[512 + b*64 + h*16 + d];
    float val = s / (qn * kn);
    // softmax over d: 16-lane groups (xor shuffles stay within the group)
    float m = val;
    #pragma unroll
    for (int o = 8; o; o >>= 1) m = fmaxf(m, __shfl_xor_sync(0xffffffffu, m, o));
    float e = expf(val - m);
    float sum = e;
    #pragma unroll
    for (int o = 8; o; o >>= 1) sum += __shfl_xor_sync(0xffffffffu, sum, o);
    g_attn[bh*256 + tid] = e / sum;
}

// ---------------- out[b,h,c,n] = sum_d attn[c,d] * V[b,h,d,n] --------------
__global__ void applyv_kernel() {
    __shared__ float As[256];
    const int b = blockIdx.z, h = blockIdx.y;
    const int tid = threadIdx.x;
    const int px0 = blockIdx.x*512 + tid*2;
    As[tid] = g_attn[(b*4 + h)*256 + tid];
    __syncthreads();
    const float* Vb = g_V + (((size_t)(b*64 + h*16)) << 16);
    ull acc[16];
    #pragma unroll
    for (int cc = 0; cc < 16; cc++) acc[cc] = 0ull;
    #pragma unroll
    for (int d = 0; d < 16; d++) {
        float2 v2 = *(const float2*)&Vb[(d << 16) + px0];
        ull vp = pk2(v2.x, v2.y);
        #pragma unroll
        for (int cc = 0; cc < 16; cc++) {
            float a = As[cc*16 + d];
            acc[cc] = fma2(pk2(a, a), vp, acc[cc]);
        }
    }
    float* Ob = g_T + (((size_t)(b*64 + h*16)) << 16);
    #pragma unroll
    for (int cc = 0; cc < 16; cc++) {
        float2 o;
        unpk2(acc[cc], o.x, o.y);
        *(float2*)&Ob[(cc << 16) + px0] = o;
    }
}

// ---------------- 3x3 conv, f32x2 packed, fused bias/relu/residual ---------
// Tile: 32x8 px, all 64 oc. 256 threads: tx(4) x ty(8) x toc(8).
// Each thread: 8 px (x-contig) x 8 oc; acc packed over oc pairs.
__global__ void __launch_bounds__(256, 2)
conv3x3_kernel(const float* __restrict__ src,
               const float* __restrict__ w,
               const float* __restrict__ bias,
               float* __restrict__ dst,
               const float* __restrict__ add1,
               const float* __restrict__ add2,
               int relu) {
    __shared__ __align__(16) float xs[10*36];   // 10 rows x 34 cols used, pitch 36
    __shared__ __align__(16) float ws[9*64];    // [tap][oc]
    const int tid = threadIdx.x;
    const int toc = tid >> 5;          // 0..7
    const int ty  = (tid >> 2) & 7;    // 0..7
    const int tx  = tid & 3;           // 0..3
    const int x0 = blockIdx.x * 32, y0 = blockIdx.y * 8;
    const int b  = blockIdx.z;
    const int oc0 = toc * 8;

    ull acc[8][4];                // [px][oc pair]; pair = (oc0+2j, oc0+2j+1)
    #pragma unroll
    for (int p = 0; p < 8; p++)
        #pragma unroll
        for (int j = 0; j < 4; j++) acc[p][j] = 0ull;

    #pragma unroll 1
    for (int ci = 0; ci < 64; ci++) {
        const float* sp = src + (((size_t)(b*64 + ci)) << 16);
        // xs: rows y0-1..y0+8 (10), cols x0-1..x0+32 (34)
        for (int e = tid; e < 340; e += 256) {
            int r = e / 34;
            int cidx = e - r*34;
            int gy = y0 + r - 1, gx = x0 + cidx - 1;
            float v = 0.f;
            if (gy >= 0 && gy < 256 && gx >= 0 && gx < 256)
                v = sp[(gy << 8) + gx];
            xs[r*36 + cidx] = v;
        }
        // ws[t*64 + oc] = w[oc][ci][t]
        for (int e = tid; e < 576; e += 256) {
            int oc = e / 9, t = e - oc*9;
            ws[t*64 + oc] = w[oc*576 + ci*9 + t];
        }
        __syncthreads();

        #pragma unroll
        for (int tr = 0; tr < 3; tr++) {
            const float* xrow = &xs[(ty + tr)*36 + 8*tx];
            float4 a = *(const float4*)&xrow[0];
            float4 bb = *(const float4*)&xrow[4];
            float4 cc = *(const float4*)&xrow[8];
            float xv[12] = {a.x, a.y, a.z, a.w, bb.x, bb.y, bb.z, bb.w,
                            cc.x, cc.y, cc.z, cc.w};
            ull xd[10];
            #pragma unroll
            for (int c = 0; c < 10; c++) xd[c] = pk2(xv[c], xv[c]);
            #pragma unroll
            for (int tc = 0; tc < 3; tc++) {
                const int t = tr*3 + tc;
                const ull* wp = (const ull*)&ws[t*64 + oc0];
                ull w0 = wp[0], w1 = wp[1], w2 = wp[2], w3 = wp[3];
                #pragma unroll
                for (int p = 0; p < 8; p++) {
                    ull xvv = xd[p + tc];
                    acc[p][0] = fma2(w0, xvv, acc[p][0]);
                    acc[p][1] = fma2(w1, xvv, acc[p][1]);
                    acc[p][2] = fma2(w2, xvv, acc[p][2]);
                    acc[p][3] = fma2(w3, xvv, acc[p][3]);
                }
            }
        }
        __syncthreads();
    }

    const int gy = y0 + ty;
    #pragma unroll
    for (int p = 0; p < 8; p++) {
        const int gx = x0 + 8*tx + p;
        const int pidx = (gy << 8) + gx;
        #pragma unroll
        for (int j = 0; j < 4; j++) {
            const int oc = oc0 + 2*j;
            float v0, v1;
            unpk2(acc[p][j], v0, v1);
            v0 += bias[oc];
            v1 += bias[oc + 1];
            if (relu) { v0 = fmaxf(v0, 0.f); v1 = fmaxf(v1, 0.f); }
            size_t i0 = (((size_t)(b*64 + oc)) << 16) + pidx;
            size_t i1 = (((size_t)(b*64 + oc + 1)) << 16) + pidx;
            if (add1) { v0 += add1[i0]; v1 += add1[i1]; }
            if (add2) { v0 += add2[i0]; v1 += add2[i1]; }
            dst[i0] = v0;
            dst[i1] = v1;
        }
    }
}

// ---------------------------------------------------------------------------
static float* sym_addr(const void* sym) {
    void* p = nullptr;
    cudaGetSymbolAddress(&p, sym);
    return (float*)p;
}

extern "C" void kernel_launch(void* const* d_in, const int* in_sizes, int n_in,
                              void* d_out, int out_size) {
    const float* x    = (const float*)d_in[0];
    const float* y    = (const float*)d_in[1];
    const float* qw   = (const float*)d_in[2];
    const float* qb   = (const float*)d_in[3];
    const float* kw   = (const float*)d_in[4];
    const float* kb   = (const float*)d_in[5];
    const float* vw   = (const float*)d_in[6];
    const float* vb   = (const float*)d_in[7];
    const float* r1w1 = (const float*)d_in[8];
    const float* r1b1 = (const float*)d_in[9];
    const float* r1w2 = (const float*)d_in[10];
    const float* r1b2 = (const float*)d_in[11];
    const float* r2w1 = (const float*)d_in[12];
    const float* r2b1 = (const float*)d_in[13];
    const float* r2w2 = (const float*)d_in[14];
    const float* r2b2 = (const float*)d_in[15];
    float* out = (float*)d_out;

    float* pQ = sym_addr(g_Q);
    float* pK = sym_addr(g_K);
    float* pV = sym_addr(g_V);
    float* pT = sym_addr(g_T);

    dim3 blk(256);

    // QKV 1x1 convs
    conv1x1_kernel<<<dim3(1024, 1, 8), blk>>>(x, qw, qb, pQ);
    conv1x1_kernel<<<dim3(1024, 1, 8), blk>>>(y, kw, kb, pK);
    conv1x1_kernel<<<dim3(1024, 1, 8), blk>>>(y, vw, vb, pV);

    // norms + attention
    norms_kernel<<<1024, blk>>>();
    attn_partial_kernel<<<dim3(32, 32), blk>>>();
    attn_finish_kernel<<<32, blk>>>();
    applyv_kernel<<<dim3(128, 4, 8), blk>>>();   // -> g_T

    dim3 cgrid(8, 32, 8);
    // residual block 1: T -> Q (relu), then K = T + conv(Q)
    conv3x3_kernel<<<cgrid, blk>>>(pT, r1w1, r1b1, pQ, nullptr, nullptr, 1);
    conv3x3_kernel<<<cgrid, blk>>>(pQ, r1w2, r1b2, pK, pT, nullptr, 0);
    // residual block 2: K -> Q (relu), then out = K + conv(Q) + y
    conv3x3_kernel<<<cgrid, blk>>>(pK, r2w1, r2b1, pQ, nullptr, nullptr, 1);
    conv3x3_kernel<<<cgrid, blk>>>(pQ, r2w2, r2b2, out, pK, y, 0);
}

// round 8
// speedup vs baseline: 1.0460x; 1.0033x over previous
#include <cuda_runtime.h>
#include <cstdint>
#include <math.h>

#define BATCH 8
#define CHN   64
#define HEADS 4
#define CHH   16
#define IMG   256
#define HW    65536
#define NTOT  (BATCH*CHN*HW)

typedef unsigned long long ull;

// ---------------- packed f32x2 helpers (attention path) --------------------
__device__ __forceinline__ ull pk2(float lo, float hi) {
    ull r;
    asm("mov.b64 %0, {%1, %2};" : "=l"(r) : "f"(lo), "f"(hi));
    return r;
}
__device__ __forceinline__ void unpk2(ull v, float& lo, float& hi) {
    asm("mov.b64 {%0, %1}, %2;" : "=f"(lo), "=f"(hi) : "l"(v));
}
__device__ __forceinline__ ull fma2(ull a, ull b, ull c) {
    ull d;
    asm("fma.rn.f32x2 %0, %1, %2, %3;" : "=l"(d) : "l"(a), "l"(b), "l"(c));
    return d;
}

// ---------------- scratch (device globals; no allocation allowed) ----------
__device__ float g_Q[NTOT];
__device__ float g_K[NTOT];
__device__ float g_V[NTOT];
__device__ float g_T[NTOT];
__device__ float g_partial[32*32*256];  // [split][bh][c*16+d]
__device__ float g_attn[32*256];        // [bh][c*16+d]
__device__ float g_norms[2*BATCH*CHN];  // [0:512)=q norms, [512:1024)=k norms

// ---------------- 1x1 conv (memory-bound, unchanged) -----------------------
__global__ void conv1x1_kernel(const float* __restrict__ src,
                               const float* __restrict__ w,
                               const float* __restrict__ bias,
                               float* __restrict__ dst) {
    __shared__ __align__(16) float Wt[64*64];   // [ci][co]
    __shared__ __align__(16) float Xs[64*64];   // [ci][px]
    const int b = blockIdx.z;
    const int pxbase = blockIdx.x * 64;
    const int tid = threadIdx.x;

    for (int e = tid; e < 4096; e += 256) {
        int ci = e >> 6, co = e & 63;
        Wt[ci*64 + co] = w[co*64 + ci];
    }
    for (int e = tid; e < 4096; e += 256) {
        int ci = e >> 6, px = e & 63;
        Xs[ci*64 + px] = src[((b*64 + ci) << 16) + pxbase + px];
    }
    __syncthreads();

    const int ty = tid >> 4, tx = tid & 15;
    const int co0 = ty*4, px0 = tx*4;
    ull acc[4][2];
    #pragma unroll
    for (int i = 0; i < 4; i++) {
        float bv = bias[co0 + i];
        acc[i][0] = pk2(bv, bv);
        acc[i][1] = pk2(bv, bv);
    }
    #pragma unroll 8
    for (int ci = 0; ci < 64; ci++) {
        float4 a4 = *(const float4*)&Wt[ci*64 + co0];
        float4 b4 = *(const float4*)&Xs[ci*64 + px0];
        ull bp0 = pk2(b4.x, b4.y);
        ull bp1 = pk2(b4.z, b4.w);
        float av[4] = {a4.x, a4.y, a4.z, a4.w};
        #pragma unroll
        for (int i = 0; i < 4; i++) {
            ull ad = pk2(av[i], av[i]);
            acc[i][0] = fma2(ad, bp0, acc[i][0]);
            acc[i][1] = fma2(ad, bp1, acc[i][1]);
        }
    }
    #pragma unroll
    for (int i = 0; i < 4; i++) {
        float4 o;
        unpk2(acc[i][0], o.x, o.y);
        unpk2(acc[i][1], o.z, o.w);
        *(float4*)&dst[((b*64 + co0 + i) << 16) + pxbase + px0] = o;
    }
}

// ---------------- per-row sum of squares for q/k L2 norms ------------------
__global__ void norms_kernel() {
    const int idx = blockIdx.x;           // 0..1023
    const float* base = (idx < 512) ? g_Q : g_K;
    const int row = idx & 511;
    const float4* p = (const float4*)(base + ((size_t)row << 16));
    const int tid = threadIdx.x;
    float s = 0.f;
    for (int i = tid; i < HW/4; i += 256) {
        float4 v = p[i];
        s += v.x*v.x + v.y*v.y + v.z*v.z + v.w*v.w;
    }
    #pragma unroll
    for (int o = 16; o; o >>= 1) s += __shfl_xor_sync(0xffffffffu, s, o);
    __shared__ float red[8];
    if ((tid & 31) == 0) red[tid >> 5] = s;
    __syncthreads();
    if (tid < 8) {
        float v = red[tid];
        #pragma unroll
        for (int o = 4; o; o >>= 1) v += __shfl_xor_sync(0xffu, v, o);
        if (tid == 0) g_norms[idx] = fmaxf(sqrtf(v), 1e-12f);
    }
}

// ---------------- q.k^T partial sums (split over n) ------------------------
__global__ void attn_partial_kernel() {
    __shared__ __align__(16) float Qs[16*132];
    __shared__ __align__(16) float Ks[16*132];
    const int bh = blockIdx.x;       // 0..31
    const int split = blockIdx.y;    // 0..31
    const int b = bh >> 2, h = bh & 3;
    const int tid = threadIdx.x;
    const int c = tid >> 4, d = tid & 15;
    const float* Qb = g_Q + (((size_t)(b*64 + h*16)) << 16);
    const float* Kb = g_K + (((size_t)(b*64 + h*16)) << 16);
    float acc = 0.f;
    const int nbase0 = split * 2048;
    #pragma unroll 1
    for (int sub = 0; sub < 16; sub++) {
        const int nb = nbase0 + sub*128;
        for (int e = tid; e < 2048; e += 256) {
            int ch = e >> 7, j = e & 127;
            Qs[ch*132 + j] = Qb[(ch << 16) + nb + j];
            Ks[ch*132 + j] = Kb[(ch << 16) + nb + j];
        }
        __syncthreads();
        const float* qrow = &Qs[c*132];
        const float* krow = &Ks[d*132];
        #pragma unroll
        for (int j = 0; j < 128; j += 4) {
            float4 qa = *(const float4*)&qrow[j];
            float4 ka = *(const float4*)&krow[j];
            acc += qa.x*ka.x + qa.y*ka.y + qa.z*ka.z + qa.w*ka.w;
        }
        __syncthreads();
    }
    g_partial[(split*32 + bh)*256 + tid] = acc;
}

// ---------------- reduce partials, apply norms, softmax --------------------
__global__ void attn_finish_kernel() {
    const int bh = blockIdx.x;
    const int b = bh >> 2, h = bh & 3;
    const int tid = threadIdx.x;
    const int c = tid >> 4, d = tid & 15;
    float s = 0.f;
    #pragma unroll
    for (int sp = 0; sp < 32; sp++) s += g_partial[(sp*32 + bh)*256 + tid];
    const float qn = g_norms[b*64 + h*16 + c];
    const float kn = g_norms[512 + b*64 + h*16 + d];
    float val = s / (qn * kn);
    float m = val;
    #pragma unroll
    for (int o = 8; o; o >>= 1) m = fmaxf(m, __shfl_xor_sync(0xffffffffu, m, o));
    float e = expf(val - m);
    float sum = e;
    #pragma unroll
    for (int o = 8; o; o >>= 1) sum += __shfl_xor_sync(0xffffffffu, sum, o);
    g_attn[bh*256 + tid] = e / sum;
}

// ---------------- out[b,h,c,n] = sum_d attn[c,d] * V[b,h,d,n] --------------
__global__ void applyv_kernel() {
    __shared__ float As[256];
    const int b = blockIdx.z, h = blockIdx.y;
    const int tid = threadIdx.x;
    const int px0 = blockIdx.x*512 + tid*2;
    As[tid] = g_attn[(b*4 + h)*256 + tid];
    __syncthreads();
    const float* Vb = g_V + (((size_t)(b*64 + h*16)) << 16);
    ull acc[16];
    #pragma unroll
    for (int cc = 0; cc < 16; cc++) acc[cc] = 0ull;
    #pragma unroll
    for (int d = 0; d < 16; d++) {
        float2 v2 = *(const float2*)&Vb[(d << 16) + px0];
        ull vp = pk2(v2.x, v2.y);
        #pragma unroll
        for (int cc = 0; cc < 16; cc++) {
            float a = As[cc*16 + d];
            acc[cc] = fma2(pk2(a, a), vp, acc[cc]);
        }
    }
    float* Ob = g_T + (((size_t)(b*64 + h*16)) << 16);
    #pragma unroll
    for (int cc = 0; cc < 16; cc++) {
        float2 o;
        unpk2(acc[cc], o.x, o.y);
        *(float2*)&Ob[(cc << 16) + px0] = o;
    }
}

// ================== 3x3 conv via tf32 mma.sync (tensor pipe) ===============
// CTA: one output row (256 px) x 64 oc. 8 warps, each 32 px x 64 oc.
// Tap-decomposed: out[oc,px] += sum_t sum_ci Wt[oc,ci] * X[ci, y+dy, x+dx].
// ci processed in 2 halves of 32. tf32 conversion at smem-store time.
#define XPITCH 776   // floats per ci slice (3 rows * 258 cols = 774, +2 pad)
#define WPITCH 72    // floats per ci row of weights (64 used, +8 pad)
#define CONV_SMEM ((32*XPITCH + 32*WPITCH) * 4)

__device__ __forceinline__ uint32_t f2tf32(float v) {
    uint32_t t;
    asm("cvt.rna.tf32.f32 %0, %1;" : "=r"(t) : "f"(v));
    return t;
}

__global__ void __launch_bounds__(256, 2)
conv3x3_tc(const float* __restrict__ src,
           const float* __restrict__ w,
           const float* __restrict__ bias,
           float* __restrict__ dst,
           const float* __restrict__ add1,
           const float* __restrict__ add2,
           int relu) {
    extern __shared__ uint32_t sm[];
    uint32_t* Xs = sm;                  // [32ci][3r][258c] pitch XPITCH
    uint32_t* Ws = sm + 32*XPITCH;      // [32ci][64oc] pitch WPITCH
    const int tid  = threadIdx.x;
    const int warp = tid >> 5, lane = tid & 31;
    const int lr = lane >> 2, lc = lane & 3;
    const int yrow = blockIdx.x, b = blockIdx.y;
    const int px0 = warp * 32;

    float acc[2][8][4];
    #pragma unroll
    for (int mf = 0; mf < 2; mf++)
        #pragma unroll
        for (int nf = 0; nf < 8; nf++)
            #pragma unroll
            for (int r = 0; r < 4; r++) acc[mf][nf][r] = 0.f;

    #pragma unroll 1
    for (int half = 0; half < 2; half++) {
        const int ci0 = half * 32;
        __syncthreads();   // prior-half fragment reads of Xs complete
        // ---- stage X tile: 32 ci x rows {y-1,y,y+1} x cols {-1..256} ----
        #pragma unroll 1
        for (int e = tid; e < 32*774; e += 256) {
            int ci = e / 774;
            int rem = e - ci*774;
            int r = rem / 258;
            int col = rem - r*258;
            int gy = yrow + r - 1, gx = col - 1;
            float v = 0.f;
            if (gy >= 0 && gy < 256 && gx >= 0 && gx < 256)
                v = src[((size_t)(b*64 + ci0 + ci) << 16) + (gy << 8) + gx];
            Xs[ci*XPITCH + r*258 + col] = f2tf32(v);
        }
        #pragma unroll 1
        for (int t = 0; t < 9; t++) {
            __syncthreads();   // Xs staged / prior tap's Ws reads done
            for (int e = tid; e < 2048; e += 256) {
                int ci = e >> 6, oc = e & 63;
                Ws[ci*WPITCH + oc] = f2tf32(w[oc*576 + (ci0 + ci)*9 + t]);
            }
            __syncthreads();
            const int tr = t / 3;            // input row index 0..2
            const int dx1 = t - tr*3;        // dx+1 in 0..2
            const uint32_t* Xb = Xs + tr*258 + dx1;
            #pragma unroll
            for (int k = 0; k < 4; k++) {
                const int kc = k*8;
                uint32_t a[2][4], bb[8][2];
                #pragma unroll
                for (int mf = 0; mf < 2; mf++) {
                    const int base = px0 + mf*16 + lr;
                    const uint32_t* x0p = Xb + (size_t)(kc + lc)*XPITCH;
                    const uint32_t* x1p = Xb + (size_t)(kc + lc + 4)*XPITCH;
                    a[mf][0] = x0p[base];
                    a[mf][1] = x0p[base + 8];
                    a[mf][2] = x1p[base];
                    a[mf][3] = x1p[base + 8];
                }
                #pragma unroll
                for (int nf = 0; nf < 8; nf++) {
                    bb[nf][0] = Ws[(kc + lc)*WPITCH + nf*8 + lr];
                    bb[nf][1] = Ws[(kc + lc + 4)*WPITCH + nf*8 + lr];
                }
                #pragma unroll
                for (int mf = 0; mf < 2; mf++)
                    #pragma unroll
                    for (int nf = 0; nf < 8; nf++) {
                        asm volatile(
                            "mma.sync.aligned.m16n8k8.row.col.f32.tf32.tf32.f32 "
                            "{%0,%1,%2,%3}, {%4,%5,%6,%7}, {%8,%9}, {%0,%1,%2,%3};"
                            : "+f"(acc[mf][nf][0]), "+f"(acc[mf][nf][1]),
                              "+f"(acc[mf][nf][2]), "+f"(acc[mf][nf][3])
                            : "r"(a[mf][0]), "r"(a[mf][1]), "r"(a[mf][2]), "r"(a[mf][3]),
                              "r"(bb[nf][0]), "r"(bb[nf][1]));
                    }
            }
        }
    }

    // ---- epilogue: bias / relu / residual adds, scattered stores ----------
    const int ybase = yrow << 8;
    #pragma unroll
    for (int mf = 0; mf < 2; mf++) {
        const int x = px0 + mf*16 + lr;   // rows x and x+8
        #pragma unroll
        for (int nf = 0; nf < 8; nf++) {
            const int oc = nf*8 + 2*lc;
            const float bv0 = bias[oc], bv1 = bias[oc + 1];
            const size_t i00 = ((size_t)(b*64 + oc) << 16) + ybase + x;
            const size_t i01 = i00 + 65536;   // oc+1
            float v0 = acc[mf][nf][0] + bv0;
            float v1 = acc[mf][nf][1] + bv1;
            float v2 = acc[mf][nf][2] + bv0;
            float v3 = acc[mf][nf][3] + bv1;
            if (relu) {
                v0 = fmaxf(v0, 0.f); v1 = fmaxf(v1, 0.f);
                v2 = fmaxf(v2, 0.f); v3 = fmaxf(v3, 0.f);
            }
            if (add1) {
                v0 += add1[i00];     v1 += add1[i01];
                v2 += add1[i00 + 8]; v3 += add1[i01 + 8];
            }
            if (add2) {
                v0 += add2[i00];     v1 += add2[i01];
                v2 += add2[i00 + 8]; v3 += add2[i01 + 8];
            }
            dst[i00]     = v0;  dst[i01]     = v1;
            dst[i00 + 8] = v2;  dst[i01 + 8] = v3;
        }
    }
}

// ---------------------------------------------------------------------------
static float* sym_addr(const void* sym) {
    void* p = nullptr;
    cudaGetSymbolAddress(&p, sym);
    return (float*)p;
}

extern "C" void kernel_launch(void* const* d_in, const int* in_sizes, int n_in,
                              void* d_out, int out_size) {
    const float* x    = (const float*)d_in[0];
    const float* y    = (const float*)d_in[1];
    const float* qw   = (const float*)d_in[2];
    const float* qb   = (const float*)d_in[3];
    const float* kw   = (const float*)d_in[4];
    const float* kb   = (const float*)d_in[5];
    const float* vw   = (const float*)d_in[6];
    const float* vb   = (const float*)d_in[7];
    const float* r1w1 = (const float*)d_in[8];
    const float* r1b1 = (const float*)d_in[9];
    const float* r1w2 = (const float*)d_in[10];
    const float* r1b2 = (const float*)d_in[11];
    const float* r2w1 = (const float*)d_in[12];
    const float* r2b1 = (const float*)d_in[13];
    const float* r2w2 = (const float*)d_in[14];
    const float* r2b2 = (const float*)d_in[15];
    float* out = (float*)d_out;

    float* pQ = sym_addr(g_Q);
    float* pK = sym_addr(g_K);
    float* pV = sym_addr(g_V);
    float* pT = sym_addr(g_T);

    cudaFuncSetAttribute(conv3x3_tc,
                         cudaFuncAttributeMaxDynamicSharedMemorySize, CONV_SMEM);

    dim3 blk(256);

    // QKV 1x1 convs
    conv1x1_kernel<<<dim3(1024, 1, 8), blk>>>(x, qw, qb, pQ);
    conv1x1_kernel<<<dim3(1024, 1, 8), blk>>>(y, kw, kb, pK);
    conv1x1_kernel<<<dim3(1024, 1, 8), blk>>>(y, vw, vb, pV);

    // norms + attention
    norms_kernel<<<1024, blk>>>();
    attn_partial_kernel<<<dim3(32, 32), blk>>>();
    attn_finish_kernel<<<32, blk>>>();
    applyv_kernel<<<dim3(128, 4, 8), blk>>>();   // -> g_T

    dim3 cgrid(256, 8);
    // residual block 1: T -> Q (relu), then K = T + conv(Q)
    conv3x3_tc<<<cgrid, blk, CONV_SMEM>>>(pT, r1w1, r1b1, pQ, nullptr, nullptr, 1);
    conv3x3_tc<<<cgrid, blk, CONV_SMEM>>>(pQ, r1w2, r1b2, pK, pT, nullptr, 0);
    // residual block 2: K -> Q (relu), then out = K + conv(Q) + y
    conv3x3_tc<<<cgrid, blk, CONV_SMEM>>>(pK, r2w1, r2b1, pQ, nullptr, nullptr, 1);
    conv3x3_tc<<<cgrid, blk, CONV_SMEM>>>(pQ, r2w2, r2b2, out, pK, y, 0);
}

// round 14
// speedup vs baseline: 2.4795x; 2.3705x over previous
#include <cuda_runtime.h>
#include <cstdint>
#include <math.h>

#define BATCH 8
#define CHN   64
#define HEADS 4
#define CHH   16
#define IMG   256
#define HW    65536
#define NTOT  (BATCH*CHN*HW)

typedef unsigned long long ull;

// ---------------- packed f32x2 helpers (attention path) --------------------
__device__ __forceinline__ ull pk2(float lo, float hi) {
    ull r;
    asm("mov.b64 %0, {%1, %2};" : "=l"(r) : "f"(lo), "f"(hi));
    return r;
}
__device__ __forceinline__ void unpk2(ull v, float& lo, float& hi) {
    asm("mov.b64 {%0, %1}, %2;" : "=f"(lo), "=f"(hi) : "l"(v));
}
__device__ __forceinline__ ull fma2(ull a, ull b, ull c) {
    ull d;
    asm("fma.rn.f32x2 %0, %1, %2, %3;" : "=l"(d) : "l"(a), "l"(b), "l"(c));
    return d;
}
__device__ __forceinline__ uint32_t f2tf32(float v) {
    uint32_t t;
    asm("cvt.rna.tf32.f32 %0, %1;" : "=r"(t) : "f"(v));
    return t;
}

// ---------------- scratch (device globals; no allocation allowed) ----------
__device__ float g_Q[NTOT];
__device__ float g_K[NTOT];
__device__ float g_V[NTOT];
__device__ float g_T[NTOT];
__device__ float g_partial[32*32*256];  // [split][bh][c*16+d]
__device__ float g_attn[32*256];        // [bh][c*16+d]
__device__ float g_norms[2*BATCH*CHN];  // [0:512)=q norms, [512:1024)=k norms
__device__ __align__(16) uint32_t g_Wt[4*64*576];  // [conv][ci][t*64+oc] tf32 bits

// ---------------- 1x1 conv (memory-bound, unchanged) -----------------------
__global__ void conv1x1_kernel(const float* __restrict__ src,
                               const float* __restrict__ w,
                               const float* __restrict__ bias,
                               float* __restrict__ dst) {
    __shared__ __align__(16) float Wt[64*64];   // [ci][co]
    __shared__ __align__(16) float Xs[64*64];   // [ci][px]
    const int b = blockIdx.z;
    const int pxbase = blockIdx.x * 64;
    const int tid = threadIdx.x;

    for (int e = tid; e < 4096; e += 256) {
        int ci = e >> 6, co = e & 63;
        Wt[ci*64 + co] = w[co*64 + ci];
    }
    for (int e = tid; e < 4096; e += 256) {
        int ci = e >> 6, px = e & 63;
        Xs[ci*64 + px] = src[((b*64 + ci) << 16) + pxbase + px];
    }
    __syncthreads();

    const int ty = tid >> 4, tx = tid & 15;
    const int co0 = ty*4, px0 = tx*4;
    ull acc[4][2];
    #pragma unroll
    for (int i = 0; i < 4; i++) {
        float bv = bias[co0 + i];
        acc[i][0] = pk2(bv, bv);
        acc[i][1] = pk2(bv, bv);
    }
    #pragma unroll 8
    for (int ci = 0; ci < 64; ci++) {
        float4 a4 = *(const float4*)&Wt[ci*64 + co0];
        float4 b4 = *(const float4*)&Xs[ci*64 + px0];
        ull bp0 = pk2(b4.x, b4.y);
        ull bp1 = pk2(b4.z, b4.w);
        float av[4] = {a4.x, a4.y, a4.z, a4.w};
        #pragma unroll
        for (int i = 0; i < 4; i++) {
            ull ad = pk2(av[i], av[i]);
            acc[i][0] = fma2(ad, bp0, acc[i][0]);
            acc[i][1] = fma2(ad, bp1, acc[i][1]);
        }
    }
    #pragma unroll
    for (int i = 0; i < 4; i++) {
        float4 o;
        unpk2(acc[i][0], o.x, o.y);
        unpk2(acc[i][1], o.z, o.w);
        *(float4*)&dst[((b*64 + co0 + i) << 16) + pxbase + px0] = o;
    }
}

// ---------------- per-row sum of squares for q/k L2 norms ------------------
__global__ void norms_kernel() {
    const int idx = blockIdx.x;           // 0..1023
    const float* base = (idx < 512) ? g_Q : g_K;
    const int row = idx & 511;
    const float4* p = (const float4*)(base + ((size_t)row << 16));
    const int tid = threadIdx.x;
    float s = 0.f;
    for (int i = tid; i < HW/4; i += 256) {
        float4 v = p[i];
        s += v.x*v.x + v.y*v.y + v.z*v.z + v.w*v.w;
    }
    #pragma unroll
    for (int o = 16; o; o >>= 1) s += __shfl_xor_sync(0xffffffffu, s, o);
    __shared__ float red[8];
    if ((tid & 31) == 0) red[tid >> 5] = s;
    __syncthreads();
    if (tid < 8) {
        float v = red[tid];
        #pragma unroll
        for (int o = 4; o; o >>= 1) v += __shfl_xor_sync(0xffu, v, o);
        if (tid == 0) g_norms[idx] = fmaxf(sqrtf(v), 1e-12f);
    }
}

// ---------------- q.k^T partial sums (split over n) ------------------------
__global__ void attn_partial_kernel() {
    __shared__ __align__(16) float Qs[16*132];
    __shared__ __align__(16) float Ks[16*132];
    const int bh = blockIdx.x;       // 0..31
    const int split = blockIdx.y;    // 0..31
    const int b = bh >> 2, h = bh & 3;
    const int tid = threadIdx.x;
    const int c = tid >> 4, d = tid & 15;
    const float* Qb = g_Q + (((size_t)(b*64 + h*16)) << 16);
    const float* Kb = g_K + (((size_t)(b*64 + h*16)) << 16);
    float acc = 0.f;
    const int nbase0 = split * 2048;
    #pragma unroll 1
    for (int sub = 0; sub < 16; sub++) {
        const int nb = nbase0 + sub*128;
        for (int e = tid; e < 2048; e += 256) {
            int ch = e >> 7, j = e & 127;
            Qs[ch*132 + j] = Qb[(ch << 16) + nb + j];
            Ks[ch*132 + j] = Kb[(ch << 16) + nb + j];
        }
        __syncthreads();
        const float* qrow = &Qs[c*132];
        const float* krow = &Ks[d*132];
        #pragma unroll
        for (int j = 0; j < 128; j += 4) {
            float4 qa = *(const float4*)&qrow[j];
            float4 ka = *(const float4*)&krow[j];
            acc += qa.x*ka.x + qa.y*ka.y + qa.z*ka.z + qa.w*ka.w;
        }
        __syncthreads();
    }
    g_partial[(split*32 + bh)*256 + tid] = acc;
}

// ---------------- reduce partials, apply norms, softmax --------------------
__global__ void attn_finish_kernel() {
    const int bh = blockIdx.x;
    const int b = bh >> 2, h = bh & 3;
    const int tid = threadIdx.x;
    const int c = tid >> 4, d = tid & 15;
    float s = 0.f;
    #pragma unroll
    for (int sp = 0; sp < 32; sp++) s += g_partial[(sp*32 + bh)*256 + tid];
    const float qn = g_norms[b*64 + h*16 + c];
    const float kn = g_norms[512 + b*64 + h*16 + d];
    float val = s / (qn * kn);
    float m = val;
    #pragma unroll
    for (int o = 8; o; o >>= 1) m = fmaxf(m, __shfl_xor_sync(0xffffffffu, m, o));
    float e = expf(val - m);
    float sum = e;
    #pragma unroll
    for (int o = 8; o; o >>= 1) sum += __shfl_xor_sync(0xffffffffu, sum, o);
    g_attn[bh*256 + tid] = e / sum;
}

// ---------------- out[b,h,c,n] = sum_d attn[c,d] * V[b,h,d,n] --------------
__global__ void applyv_kernel() {
    __shared__ float As[256];
    const int b = blockIdx.z, h = blockIdx.y;
    const int tid = threadIdx.x;
    const int px0 = blockIdx.x*512 + tid*2;
    As[tid] = g_attn[(b*4 + h)*256 + tid];
    __syncthreads();
    const float* Vb = g_V + (((size_t)(b*64 + h*16)) << 16);
    ull acc[16];
    #pragma unroll
    for (int cc = 0; cc < 16; cc++) acc[cc] = 0ull;
    #pragma unroll
    for (int d = 0; d < 16; d++) {
        float2 v2 = *(const float2*)&Vb[(d << 16) + px0];
        ull vp = pk2(v2.x, v2.y);
        #pragma unroll
        for (int cc = 0; cc < 16; cc++) {
            float a = As[cc*16 + d];
            acc[cc] = fma2(pk2(a, a), vp, acc[cc]);
        }
    }
    float* Ob = g_T + (((size_t)(b*64 + h*16)) << 16);
    #pragma unroll
    for (int cc = 0; cc < 16; cc++) {
        float2 o;
        unpk2(acc[cc], o.x, o.y);
        *(float2*)&Ob[(cc << 16) + px0] = o;
    }
}

// ---------------- weight prep: transpose + tf32-convert once ---------------
// g_Wt[c][ci*576 + t*64 + oc] = tf32(w_c[oc*576 + ci*9 + t])
__global__ void prep_weights(const float* __restrict__ w0, const float* __restrict__ w1,
                             const float* __restrict__ w2, const float* __restrict__ w3) {
    const float* ws[4] = {w0, w1, w2, w3};
    const float* w = ws[blockIdx.y];
    uint32_t* o = g_Wt + blockIdx.y * 36864;
    for (int e = blockIdx.x*256 + threadIdx.x; e < 36864; e += gridDim.x*256) {
        int ci = e / 576, rem = e - ci*576;
        int t = rem >> 6, oc = rem & 63;
        o[e] = f2tf32(w[oc*576 + ci*9 + t]);
    }
}

// ================== 3x3 conv via tf32 mma.sync (tensor pipe) ===============
// CTA: one output row (256 px) x 64 oc. 8 warps, each 32 px x 64 oc.
// ci in 4 quarters of 16; per quarter: stage X (batched LDG.128) + all-9-tap
// weights (coalesced from g_Wt), then 9 taps x 2 k-steps of MMAs, 2 syncs.
#define XRP   264   // row pitch (cols at index 3..260; col c -> 3+c)
#define XCIP  808   // ci pitch = 3*264 + pad8 (mod 32 == 8 -> conflict-free)
#define WCIP  584   // weight ci pitch = 9*64 + 8 (mod 32 == 8)
#define CONV_SMEM ((16*XCIP + 16*WCIP) * 4)   // 89088 bytes

__global__ void __launch_bounds__(256, 2)
conv3x3_tc(const float* __restrict__ src,
           const uint32_t* __restrict__ wt,
           const float* __restrict__ bias,
           float* __restrict__ dst,
           const float* __restrict__ add1,
           const float* __restrict__ add2,
           int relu) {
    extern __shared__ uint32_t sm[];
    uint32_t* Xs = sm;                  // [16ci][3r][XRP]
    uint32_t* Ws = sm + 16*XCIP;        // [16ci][9t*64oc] pitch WCIP
    const int tid  = threadIdx.x;
    const int warp = tid >> 5, lane = tid & 31;
    const int lr = lane >> 2, lc = lane & 3;
    const int yrow = blockIdx.x, b = blockIdx.y;
    const int px0 = warp * 32;

    float acc[2][8][4];
    #pragma unroll
    for (int mf = 0; mf < 2; mf++)
        #pragma unroll
        for (int nf = 0; nf < 8; nf++)
            #pragma unroll
            for (int r = 0; r < 4; r++) acc[mf][nf][r] = 0.f;

    // zero the always-zero halo columns (gx=-1, gx=256) once
    if (tid < 96) {
        int ci = tid / 6, rem = tid - ci*6;
        int r = rem >> 1, side = rem & 1;
        Xs[ci*XCIP + r*XRP + (side ? 260 : 3)] = 0;
    }

    #pragma unroll 1
    for (int q = 0; q < 4; q++) {
        const int ci0 = q * 16;
        __syncthreads();    // prior-quarter reads done (q=0: halo writes visible)
        // ---- X interior: 16ci x 3r x 64 float4, 12 per thread, batched ----
        #pragma unroll
        for (int i = 0; i < 12; i++) {
            const int e = i*256 + tid;
            const int ci = e / 192;
            const int rem = e - ci*192;
            const int r = rem >> 6, c4 = rem & 63;
            const int gy = yrow + r - 1;
            uint4 o = make_uint4(0u, 0u, 0u, 0u);
            if (gy >= 0 && gy < 256) {
                float4 v = *(const float4*)&src[((size_t)(b*64 + ci0 + ci) << 16) + (gy << 8) + 4*c4];
                o.x = f2tf32(v.x); o.y = f2tf32(v.y);
                o.z = f2tf32(v.z); o.w = f2tf32(v.w);
            }
            *(uint4*)&Xs[ci*XCIP + r*XRP + 4 + 4*c4] = o;
        }
        // ---- weights: 16ci x 144 uint4, 9 per thread, coalesced copy ----
        const uint4* wq = (const uint4*)(wt + ci0*576);
        #pragma unroll
        for (int i = 0; i < 9; i++) {
            const int e = i*256 + tid;
            const int ci = e / 144;
            const int f4 = e - ci*144;
            *(uint4*)&Ws[ci*WCIP + 4*f4] = wq[ci*144 + f4];
        }
        __syncthreads();

        #pragma unroll
        for (int t = 0; t < 9; t++) {
            const int tr = t / 3;
            const int dx = t - tr*3;
            const uint32_t* Xb = Xs + tr*XRP + 3 + dx;
            #pragma unroll
            for (int k = 0; k < 2; k++) {
                const int kc = k*8;
                uint32_t a[2][4], bb[8][2];
                #pragma unroll
                for (int mf = 0; mf < 2; mf++) {
                    const int base = px0 + mf*16 + lr;
                    const uint32_t* x0p = Xb + (kc + lc)*XCIP;
                    const uint32_t* x1p = Xb + (kc + lc + 4)*XCIP;
                    a[mf][0] = x0p[base];
                    a[mf][1] = x0p[base + 8];
                    a[mf][2] = x1p[base];
                    a[mf][3] = x1p[base + 8];
                }
                #pragma unroll
                for (int nf = 0; nf < 8; nf++) {
                    bb[nf][0] = Ws[(kc + lc)*WCIP + t*64 + nf*8 + lr];
                    bb[nf][1] = Ws[(kc + lc + 4)*WCIP + t*64 + nf*8 + lr];
                }
                #pragma unroll
                for (int mf = 0; mf < 2; mf++)
                    #pragma unroll
                    for (int nf = 0; nf < 8; nf++) {
                        asm volatile(
                            "mma.sync.aligned.m16n8k8.row.col.f32.tf32.tf32.f32 "
                            "{%0,%1,%2,%3}, {%4,%5,%6,%7}, {%8,%9}, {%0,%1,%2,%3};"
                            : "+f"(acc[mf][nf][0]), "+f"(acc[mf][nf][1]),
                              "+f"(acc[mf][nf][2]), "+f"(acc[mf][nf][3])
                            : "r"(a[mf][0]), "r"(a[mf][1]), "r"(a[mf][2]), "r"(a[mf][3]),
                              "r"(bb[nf][0]), "r"(bb[nf][1]));
                    }
            }
        }
    }

    // ---- epilogue: bias / relu / residual adds ----------------------------
    const int ybase = yrow << 8;
    #pragma unroll
    for (int mf = 0; mf < 2; mf++) {
        const int x = px0 + mf*16 + lr;   // px rows x and x+8
        #pragma unroll
        for (int nf = 0; nf < 8; nf++) {
            const int oc = nf*8 + 2*lc;
            const float bv0 = bias[oc], bv1 = bias[oc + 1];
            const size_t i00 = ((size_t)(b*64 + oc) << 16) + ybase + x;
            const size_t i01 = i00 + 65536;   // oc+1
            float v0 = acc[mf][nf][0] + bv0;
            float v1 = acc[mf][nf][1] + bv1;
            float v2 = acc[mf][nf][2] + bv0;
            float v3 = acc[mf][nf][3] + bv1;
            if (relu) {
                v0 = fmaxf(v0, 0.f); v1 = fmaxf(v1, 0.f);
                v2 = fmaxf(v2, 0.f); v3 = fmaxf(v3, 0.f);
            }
            if (add1) {
                v0 += add1[i00];     v1 += add1[i01];
                v2 += add1[i00 + 8]; v3 += add1[i01 + 8];
            }
            if (add2) {
                v0 += add2[i00];     v1 += add2[i01];
                v2 += add2[i00 + 8]; v3 += add2[i01 + 8];
            }
            dst[i00]     = v0;  dst[i01]     = v1;
            dst[i00 + 8] = v2;  dst[i01 + 8] = v3;
        }
    }
}

// ---------------------------------------------------------------------------
static float* sym_addr(const void* sym) {
    void* p = nullptr;
    cudaGetSymbolAddress(&p, sym);
    return (float*)p;
}

extern "C" void kernel_launch(void* const* d_in, const int* in_sizes, int n_in,
                              void* d_out, int out_size) {
    const float* x    = (const float*)d_in[0];
    const float* y    = (const float*)d_in[1];
    const float* qw   = (const float*)d_in[2];
    const float* qb   = (const float*)d_in[3];
    const float* kw   = (const float*)d_in[4];
    const float* kb   = (const float*)d_in[5];
    const float* vw   = (const float*)d_in[6];
    const float* vb   = (const float*)d_in[7];
    const float* r1w1 = (const float*)d_in[8];
    const float* r1b1 = (const float*)d_in[9];
    const float* r1w2 = (const float*)d_in[10];
    const float* r1b2 = (const float*)d_in[11];
    const float* r2w1 = (const float*)d_in[12];
    const float* r2b1 = (const float*)d_in[13];
    const float* r2w2 = (const float*)d_in[14];
    const float* r2b2 = (const float*)d_in[15];
    float* out = (float*)d_out;

    float* pQ = sym_addr(g_Q);
    float* pK = sym_addr(g_K);
    float* pV = sym_addr(g_V);
    float* pT = sym_addr(g_T);
    uint32_t* pWt = nullptr;
    { void* p = nullptr; cudaGetSymbolAddress(&p, g_Wt); pWt = (uint32_t*)p; }

    cudaFuncSetAttribute(conv3x3_tc,
                         cudaFuncAttributeMaxDynamicSharedMemorySize, CONV_SMEM);

    dim3 blk(256);

    // weight prep (independent of data path; overlaps QKV convs on the stream order)
    prep_weights<<<dim3(36, 4), blk>>>(r1w1, r1w2, r2w1, r2w2);

    // QKV 1x1 convs
    conv1x1_kernel<<<dim3(1024, 1, 8), blk>>>(x, qw, qb, pQ);
    conv1x1_kernel<<<dim3(1024, 1, 8), blk>>>(y, kw, kb, pK);
    conv1x1_kernel<<<dim3(1024, 1, 8), blk>>>(y, vw, vb, pV);

    // norms + attention
    norms_kernel<<<1024, blk>>>();
    attn_partial_kernel<<<dim3(32, 32), blk>>>();
    attn_finish_kernel<<<32, blk>>>();
    applyv_kernel<<<dim3(128, 4, 8), blk>>>();   // -> g_T

    dim3 cgrid(256, 8);
    // residual block 1: T -> Q (relu), then K = T + conv(Q)
    conv3x3_tc<<<cgrid, blk, CONV_SMEM>>>(pT, pWt + 0*36864, r1b1, pQ, nullptr, nullptr, 1);
    conv3x3_tc<<<cgrid, blk, CONV_SMEM>>>(pQ, pWt + 1*36864, r1b2, pK, pT, nullptr, 0);
    // residual block 2: K -> Q (relu), then out = K + conv(Q) + y
    conv3x3_tc<<<cgrid, blk, CONV_SMEM>>>(pK, pWt + 2*36864, r2b1, pQ, nullptr, nullptr, 1);
    conv3x3_tc<<<cgrid, blk, CONV_SMEM>>>(pQ, pWt + 3*36864, r2b2, out, pK, y, 0);
}